// round 2
// baseline (speedup 1.0000x reference)
#include <cuda_runtime.h>
#include <cstdint>

#define T_STEPS 4096
#define BATCH   64
#define NH      128
#define NROWS   (BATCH * T_STEPS)   // 262144

// Scratch (allocation-free rule: __device__ globals)
__device__ float g_xp[(size_t)NROWS * NH];  // x_proj = input @ W1x^T + b1
__device__ float g_h [(size_t)NROWS * NH];  // hidden state sequence

// ---------------------------------------------------------------------------
// Helpers
// ---------------------------------------------------------------------------
__device__ __forceinline__ uint64_t ffma2(uint64_t a, uint64_t b, uint64_t c) {
    uint64_t d;
    asm("fma.rn.f32x2 %0, %1, %2, %3;" : "=l"(d) : "l"(a), "l"(b), "l"(c));
    return d;
}
__device__ __forceinline__ float f2sum(uint64_t v) {
    float lo = __uint_as_float((uint32_t)v);
    float hi = __uint_as_float((uint32_t)(v >> 32));
    return lo + hi;
}
__device__ __forceinline__ void cp_async4(uint32_t saddr, const float* g) {
    asm volatile("cp.async.ca.shared.global [%0], [%1], 4;" :: "r"(saddr), "l"(g));
}
__device__ __forceinline__ void cp_commit() { asm volatile("cp.async.commit_group;"); }
__device__ __forceinline__ void cp_wait2()  { asm volatile("cp.async.wait_group 2;" ::: "memory"); }

// ---------------------------------------------------------------------------
// Parallel GEMM: out[r, j] = (relu?)( sum_i in[r, i] * W[j, woff + i] + bias[j] )
// 128 threads/block, thread j owns W row j in registers (64 x f32x2).
// 4-stage cp.async ring for input rows.
// ---------------------------------------------------------------------------
template<bool RELU>
__global__ void __launch_bounds__(128, 2) gemm128_kernel(
    const float* __restrict__ in, const float* __restrict__ W,
    int wstride, int woff,
    const float* __restrict__ bias, float* __restrict__ out,
    int rows_per_block)
{
    __shared__ __align__(16) float rowbuf[4][NH];
    const int j = threadIdx.x;
    const size_t base = (size_t)blockIdx.x * rows_per_block;

    uint64_t w[64];
#pragma unroll
    for (int k = 0; k < 64; k++)
        w[k] = *reinterpret_cast<const uint64_t*>(&W[(size_t)j * wstride + woff + 2 * k]);
    const float bj = bias[j];

    const uint32_t sb = (uint32_t)__cvta_generic_to_shared(&rowbuf[0][0]);

#pragma unroll
    for (int s = 0; s < 3; s++) {
        cp_async4(sb + (uint32_t)(s * NH + j) * 4, &in[(base + s) * NH + j]);
        cp_commit();
    }

    for (int r = 0; r < rows_per_block; r++) {
        cp_wait2();          // stage r%4 landed (this thread's element + all others')
        __syncthreads();     // make all threads' stage data + prior reads visible/done
        const int pr = r + 3;
        if (pr < rows_per_block)
            cp_async4(sb + (uint32_t)((pr & 3) * NH + j) * 4, &in[(base + pr) * NH + j]);
        cp_commit();

        const float* row = rowbuf[r & 3];
        uint64_t a0 = 0, a1 = 0;
#pragma unroll
        for (int k = 0; k < 32; k++) {
            ulonglong2 hv = *reinterpret_cast<const ulonglong2*>(&row[4 * k]);
            a0 = ffma2(w[2 * k],     hv.x, a0);
            a1 = ffma2(w[2 * k + 1], hv.y, a1);
        }
        float s = f2sum(a0) + f2sum(a1) + bj;
        if (RELU) s = fmaxf(s, 0.0f);
        out[(base + r) * NH + j] = s;
    }
}

// ---------------------------------------------------------------------------
// Sequential scan: h_t = relu(W1h @ h_{t-1} + xp_t), writes full h sequence.
// 64 blocks (one batch row each), 128 threads. Thread j owns W1h row j in
// registers. h double-buffered in SMEM (broadcast LDS.128). xp streamed via
// 4-stage cp.async ring (each thread consumes only its own element -> no
// extra barrier needed for xp).
// ---------------------------------------------------------------------------
__global__ void __launch_bounds__(128, 1) rnn_scan_kernel(
    const float* __restrict__ W1, float* __restrict__ hseq)
{
    __shared__ __align__(16) float hbuf[2][NH];
    __shared__ __align__(16) float xpbuf[4][NH];
    const int j = threadIdx.x;
    const int b = blockIdx.x;

    const float* xp = g_xp + (size_t)b * T_STEPS * NH;
    float*       hs = hseq + (size_t)b * T_STEPS * NH;

    uint64_t w[64];
#pragma unroll
    for (int k = 0; k < 64; k++)
        w[k] = *reinterpret_cast<const uint64_t*>(&W1[(size_t)j * 256 + 2 * k]);  // W1h = W1[:, :128]

    hbuf[0][j] = 0.0f;  // h_0 = 0

    const uint32_t sx = (uint32_t)__cvta_generic_to_shared(&xpbuf[0][0]);
#pragma unroll
    for (int s = 0; s < 3; s++) {
        cp_async4(sx + (uint32_t)(s * NH + j) * 4, &xp[(size_t)s * NH + j]);
        cp_commit();
    }

    for (int t = 0; t < T_STEPS; t++) {
        cp_wait2();          // xpbuf[t%4][j] ready (own element, no barrier needed)
        __syncthreads();     // h_{t} (written previous iter) visible; WAR safe
        const int pt = t + 3;
        if (pt < T_STEPS)
            cp_async4(sx + (uint32_t)((pt & 3) * NH + j) * 4, &xp[(size_t)pt * NH + j]);
        cp_commit();

        const float* hp = hbuf[t & 1];
        uint64_t a0 = 0, a1 = 0;
#pragma unroll
        for (int k = 0; k < 32; k++) {
            ulonglong2 hv = *reinterpret_cast<const ulonglong2*>(&hp[4 * k]);
            a0 = ffma2(w[2 * k],     hv.x, a0);
            a1 = ffma2(w[2 * k + 1], hv.y, a1);
        }
        float s = f2sum(a0) + f2sum(a1) + xpbuf[t & 3][j];
        s = fmaxf(s, 0.0f);
        hbuf[(t + 1) & 1][j] = s;       // next step's input (SMEM)
        hs[(size_t)t * NH + j] = s;     // for output projection (GMEM, fire-and-forget)
    }
}

// ---------------------------------------------------------------------------
// Launch: xp GEMM -> scan -> output GEMM
// ---------------------------------------------------------------------------
extern "C" void kernel_launch(void* const* d_in, const int* in_sizes, int n_in,
                              void* d_out, int out_size)
{
    const float* input = (const float*)d_in[0];   // (64, 4096, 128)
    const float* W1    = (const float*)d_in[1];   // (128, 256)
    const float* b1    = (const float*)d_in[2];   // (128,)
    const float* W2    = (const float*)d_in[3];   // (128, 128)
    const float* b2    = (const float*)d_in[4];   // (128,)
    float* out = (float*)d_out;

    float *xp_ptr, *h_ptr;
    cudaGetSymbolAddress((void**)&xp_ptr, g_xp);
    cudaGetSymbolAddress((void**)&h_ptr,  g_h);

    const int rows_per_block = 256;               // 1024 blocks
    const int nblocks = NROWS / rows_per_block;

    // xp = input @ W1x^T + b1   (W1x = W1[:, 128:256], row stride 256)
    gemm128_kernel<false><<<nblocks, 128>>>(input, W1, 256, 128, b1, xp_ptr, rows_per_block);

    // h sequence (sequential scan, 64 independent chains)
    rnn_scan_kernel<<<BATCH, 128>>>(W1, h_ptr);

    // out = relu(h @ W2^T + b2)
    gemm128_kernel<true><<<nblocks, 128>>>(h_ptr, W2, 128, 0, b2, out, rows_per_block);
}

// round 3
// speedup vs baseline: 1.9012x; 1.9012x over previous
#include <cuda_runtime.h>
#include <cstdint>

#define T_STEPS 4096
#define BATCH   64
#define NH      128
#define NROWS   (BATCH * T_STEPS)   // 262144

// Scratch (allocation-free rule: __device__ globals).
// g_xp padded by 8 steps so the scan's register-ring prefetch never branches.
__device__ float g_xp[((size_t)NROWS + 8) * NH];
__device__ float g_h [(size_t)NROWS * NH];

// ---------------------------------------------------------------------------
// Helpers
// ---------------------------------------------------------------------------
__device__ __forceinline__ uint64_t ffma2(uint64_t a, uint64_t b, uint64_t c) {
    uint64_t d;
    asm("fma.rn.f32x2 %0, %1, %2, %3;" : "=l"(d) : "l"(a), "l"(b), "l"(c));
    return d;
}
__device__ __forceinline__ float f2sum(uint64_t v) {
    float lo = __uint_as_float((uint32_t)v);
    float hi = __uint_as_float((uint32_t)(v >> 32));
    return lo + hi;
}
__device__ __forceinline__ void cp_async16(uint32_t saddr, const void* g) {
    asm volatile("cp.async.cg.shared.global [%0], [%1], 16;" :: "r"(saddr), "l"(g));
}
__device__ __forceinline__ void cp_commit() { asm volatile("cp.async.commit_group;"); }
__device__ __forceinline__ void cp_wait1()  { asm volatile("cp.async.wait_group 1;" ::: "memory"); }

// ---------------------------------------------------------------------------
// Parallel GEMM: out[r, j] = (relu?)( sum_i in[r, i] * W[j, woff + i] + bias[j] )
// 128 threads/block, thread j owns W row j in registers (64 x f32x2).
// 16-row chunks, double-buffered cp.async (prefetch distance ~2000 cyc > DRAM
// latency). Two barriers per 16 rows.
// ---------------------------------------------------------------------------
#define CH 16   // rows per chunk

template<bool RELU>
__global__ void __launch_bounds__(128, 2) gemm128_kernel(
    const float* __restrict__ in, const float* __restrict__ W,
    int wstride, int woff,
    const float* __restrict__ bias, float* __restrict__ out,
    int rows_per_block)
{
    __shared__ __align__(16) float buf[2][CH * NH];   // 2 x 8KB
    const int j = threadIdx.x;
    const size_t base = (size_t)blockIdx.x * rows_per_block;

    uint64_t w[64];
#pragma unroll
    for (int k = 0; k < 64; k++)
        w[k] = *reinterpret_cast<const uint64_t*>(&W[(size_t)j * wstride + woff + 2 * k]);
    const float bj = bias[j];

    const uint32_t sb = (uint32_t)__cvta_generic_to_shared(&buf[0][0]);
    const float4* gsrc = reinterpret_cast<const float4*>(in + base * NH);
    const int f4_per_chunk = CH * NH / 4;   // 512 float4 per chunk

    // prologue: chunk 0 -> stage 0  (each thread: 4 x 16B, coalesced)
#pragma unroll
    for (int k = 0; k < 4; k++)
        cp_async16(sb + (uint32_t)(j + k * 128) * 16, gsrc + j + k * 128);
    cp_commit();

    const int nch = rows_per_block / CH;
    for (int c = 0; c < nch; c++) {
        // prefetch chunk c+1 into the other stage
        if (c + 1 < nch) {
            const float4* g = gsrc + (size_t)(c + 1) * f4_per_chunk;
            const uint32_t dst = sb + (uint32_t)((c + 1) & 1) * (CH * NH * 4);
#pragma unroll
            for (int k = 0; k < 4; k++)
                cp_async16(dst + (uint32_t)(j + k * 128) * 16, g + j + k * 128);
        }
        cp_commit();
        cp_wait1();          // chunk c's group complete (1 group may stay in flight)
        __syncthreads();     // visibility of all threads' cp.async data

        const float* stage = buf[c & 1];
#pragma unroll 4
        for (int r = 0; r < CH; r++) {
            const float* row = stage + r * NH;
            uint64_t a0 = 0, a1 = 0;
#pragma unroll
            for (int k = 0; k < 32; k++) {
                ulonglong2 hv = *reinterpret_cast<const ulonglong2*>(&row[4 * k]);
                a0 = ffma2(w[2 * k],     hv.x, a0);
                a1 = ffma2(w[2 * k + 1], hv.y, a1);
            }
            float s = f2sum(a0) + f2sum(a1) + bj;
            if (RELU) s = fmaxf(s, 0.0f);
            out[(base + (size_t)c * CH + r) * NH + j] = s;
        }
        __syncthreads();     // all reads of this stage done before it is refilled
    }
}

// ---------------------------------------------------------------------------
// Sequential scan: h_t = relu(W1h @ h_{t-1} + xp_t), writes full h sequence.
// 64 blocks (one batch row each), 128 threads. Thread j owns W1h row j in
// registers. h double-buffered in SMEM (broadcast LDS.128). xp prefetched via
// an 8-deep LDG register ring (loop unrolled x8, no cp.async in the serial
// loop, no bounds branch thanks to g_xp padding).
// ---------------------------------------------------------------------------
__global__ void __launch_bounds__(128, 1) rnn_scan_kernel(
    const float* __restrict__ W1, float* __restrict__ hseq)
{
    __shared__ __align__(16) float hbuf[2][NH];
    const int j = threadIdx.x;
    const int b = blockIdx.x;

    const float* xp = g_xp + (size_t)b * T_STEPS * NH;
    float*       hs = hseq + (size_t)b * T_STEPS * NH;

    uint64_t w[64];
#pragma unroll
    for (int k = 0; k < 64; k++)
        w[k] = *reinterpret_cast<const uint64_t*>(&W1[(size_t)j * 256 + 2 * k]);  // W1h = W1[:, :128]

    hbuf[0][j] = 0.0f;  // h_0 = 0

    float xr[8];
#pragma unroll
    for (int u = 0; u < 8; u++)
        xr[u] = xp[(size_t)u * NH + j];

    for (int t0 = 0; t0 < T_STEPS; t0 += 8) {
#pragma unroll
        for (int u = 0; u < 8; u++) {
            const int t = t0 + u;
            __syncthreads();                 // h_t written last step now visible; WAR safe
            const float* hp = hbuf[u & 1];   // t&1 == u&1 (t0 multiple of 8)
            uint64_t a0 = 0, a1 = 0;
#pragma unroll
            for (int k = 0; k < 32; k++) {
                ulonglong2 hv = *reinterpret_cast<const ulonglong2*>(&hp[4 * k]);
                a0 = ffma2(w[2 * k],     hv.x, a0);
                a1 = ffma2(w[2 * k + 1], hv.y, a1);
            }
            float s = f2sum(a0) + f2sum(a1) + xr[u];
            s = fmaxf(s, 0.0f);
            hbuf[(u + 1) & 1][j] = s;        // next step's input (SMEM)
            hs[(size_t)t * NH + j] = s;      // for output projection (fire-and-forget)
            xr[u] = xp[(size_t)(t + 8) * NH + j];   // refill ring (padded, no branch)
        }
    }
}

// ---------------------------------------------------------------------------
// Launch: xp GEMM -> scan -> output GEMM
// ---------------------------------------------------------------------------
extern "C" void kernel_launch(void* const* d_in, const int* in_sizes, int n_in,
                              void* d_out, int out_size)
{
    const float* input = (const float*)d_in[0];   // (64, 4096, 128)
    const float* W1    = (const float*)d_in[1];   // (128, 256)
    const float* b1    = (const float*)d_in[2];   // (128,)
    const float* W2    = (const float*)d_in[3];   // (128, 128)
    const float* b2    = (const float*)d_in[4];   // (128,)
    float* out = (float*)d_out;

    float *xp_ptr, *h_ptr;
    cudaGetSymbolAddress((void**)&xp_ptr, g_xp);
    cudaGetSymbolAddress((void**)&h_ptr,  g_h);

    const int rows_per_block = 256;               // 1024 blocks
    const int nblocks = NROWS / rows_per_block;

    // xp = input @ W1x^T + b1   (W1x = W1[:, 128:256], row stride 256)
    gemm128_kernel<false><<<nblocks, 128>>>(input, W1, 256, 128, b1, xp_ptr, rows_per_block);

    // h sequence (sequential scan, 64 independent chains)
    rnn_scan_kernel<<<BATCH, 128>>>(W1, h_ptr);

    // out = relu(h @ W2^T + b2)
    gemm128_kernel<true><<<nblocks, 128>>>(h_ptr, W2, 128, 0, b2, out, rows_per_block);
}